// round 4
// baseline (speedup 1.0000x reference)
#include <cuda_runtime.h>
#include <cstdint>
#include <math.h>

#define BB 64
#define MM 8192
#define VV 128
#define FEPS 1e-8f
#define SEL_CAP 1024

// Scratch (device globals: no allocation allowed in kernel_launch)
__device__ float g_sim[BB * MM];   // 2 MB similarity per slot

// ---- order-preserving float<->uint key mapping (larger float => larger key) ----
__device__ __forceinline__ unsigned f2k(float f) {
    unsigned b = __float_as_uint(f);
    return (b & 0x80000000u) ? ~b : (b | 0x80000000u);
}
__device__ __forceinline__ float k2f(unsigned u) {
    unsigned b = (u & 0x80000000u) ? (u ^ 0x80000000u) : ~u;
    return __uint_as_float(b);
}

// ============================================================================
// Pass 1: sim[b,m] = dot(mem[b,m]+eps, v[b]+eps) / max(||mem+eps||*||v+eps||, eps)
// Layout: 4 lanes per row, 8 rows per warp, 8 independent float4 loads per lane
// (MLP=8/thread), 2-level butterfly shared by all 8 rows of the warp.
// 256 threads -> 64 rows/tile, 2 tiles/block. Grid: (MM/128, BB).
// ============================================================================
__global__ void __launch_bounds__(256) sim_kernel(const float* __restrict__ mem,
                                                  const float* __restrict__ vin) {
    __shared__ __align__(16) float sv[VV];
    __shared__ float s_nb;
    const int b   = blockIdx.y;
    const int tid = threadIdx.x;

    if (tid < VV) sv[tid] = vin[b * VV + tid] + FEPS;
    __syncthreads();
    if (tid < 32) {
        float s = 0.f;
        #pragma unroll
        for (int i = tid; i < VV; i += 32) { float x = sv[i]; s += x * x; }
        #pragma unroll
        for (int o = 16; o; o >>= 1) s += __shfl_xor_sync(0xffffffffu, s, o);
        if (tid == 0) s_nb = sqrtf(s);
    }
    __syncthreads();

    const float nb   = s_nb;
    const int   warp = tid >> 5;
    const int   lane = tid & 31;
    const int   rw   = lane >> 2;   // row within warp's 8-row group (0..7)
    const int   s    = lane & 3;    // float4 segment base within row (0..3)

    const float4* svq = reinterpret_cast<const float4*>(sv);

    #pragma unroll
    for (int it = 0; it < 2; it++) {
        const int m = blockIdx.x * 128 + it * 64 + warp * 8 + rw;
        const float4* row = reinterpret_cast<const float4*>(
            mem + ((size_t)b * MM + m) * VV);
        // 8 independent 16B loads -> MLP 8 per thread
        float4 x0 = row[s];      float4 x1 = row[s + 4];
        float4 x2 = row[s + 8];  float4 x3 = row[s + 12];
        float4 x4 = row[s + 16]; float4 x5 = row[s + 20];
        float4 x6 = row[s + 24]; float4 x7 = row[s + 28];

        float num = 0.f, ss = 0.f;
        #define ACC(X, QI)                                            \
            { float4 Q = svq[QI];                                     \
              float a0 = X.x + FEPS, a1 = X.y + FEPS,                 \
                    a2 = X.z + FEPS, a3 = X.w + FEPS;                 \
              num += a0 * Q.x + a1 * Q.y + a2 * Q.z + a3 * Q.w;       \
              ss  += a0 * a0 + a1 * a1 + a2 * a2 + a3 * a3; }
        ACC(x0, s)      ACC(x1, s + 4)  ACC(x2, s + 8)  ACC(x3, s + 12)
        ACC(x4, s + 16) ACC(x5, s + 20) ACC(x6, s + 24) ACC(x7, s + 28)
        #undef ACC

        // reduce across the 4 lanes of this row (xor 1,2)
        #pragma unroll
        for (int o = 2; o; o >>= 1) {
            num += __shfl_xor_sync(0xffffffffu, num, o);
            ss  += __shfl_xor_sync(0xffffffffu, ss,  o);
        }
        if (s == 0)
            g_sim[b * MM + m] = num / fmaxf(sqrtf(ss) * nb, FEPS);
    }
}

// ============================================================================
// Pass 2 (fused select + read): per-batch exact kth-largest via 4-round 8-bit
// MSB radix select with WARP-AGGREGATED histograms (cosine sims cluster into
// few bins -> plain shared atomics serialize), compaction of sim >= kth, then
//   out[b,:] = sum_sel w*mem[b,m,:] + (sum_sel w^2)*v[b,:]
// One block of 1024 threads per batch.
// ============================================================================
__global__ void __launch_bounds__(1024) select_read_kernel(
        const int* __restrict__ topk_ptr,
        const float* __restrict__ mem,
        const float* __restrict__ vin,
        float* __restrict__ out) {
    __shared__ unsigned keys[MM];        // 32 KB
    __shared__ int      hist[256];
    __shared__ int      wsum[8];
    __shared__ unsigned s_prefix;
    __shared__ int      s_k, s_cnt;
    __shared__ int      s_idx[SEL_CAP];
    __shared__ float    s_w[SEL_CAP];
    __shared__ float    s_part[8][VV];   // 4 KB partial read accumulators
    __shared__ float    s_sw2;

    const int b    = blockIdx.x;
    const int tid  = threadIdx.x;
    const int lane = tid & 31;

    for (int i = tid; i < MM; i += 1024)
        keys[i] = f2k(g_sim[b * MM + i]);
    if (tid == 0) { s_prefix = 0u; s_k = *topk_ptr; s_cnt = 0; }
    __syncthreads();

    #pragma unroll
    for (int shift = 24; shift >= 0; shift -= 8) {
        if (tid < 256) hist[tid] = 0;
        __syncthreads();
        const unsigned pmask  = (shift == 24) ? 0u : (0xFFFFFFFFu << (shift + 8));
        const unsigned prefix = s_prefix;
        for (int i = tid; i < MM; i += 1024) {
            unsigned u = keys[i];
            bool act = ((u & pmask) == prefix);
            unsigned amask = __ballot_sync(0xffffffffu, act);
            if (act) {
                unsigned bin   = (u >> shift) & 255u;
                unsigned peers = __match_any_sync(amask, bin);
                if (lane == (__ffs(peers) - 1))
                    atomicAdd(&hist[bin], __popc(peers));
            }
        }
        __syncthreads();
        // two-stage top-down scan: 8 warp sums, then <=40 serial steps
        if (tid < 256) {
            int v = hist[tid];
            #pragma unroll
            for (int o = 16; o; o >>= 1) v += __shfl_xor_sync(0xffffffffu, v, o);
            if ((tid & 31) == 0) wsum[tid >> 5] = v;
        }
        __syncthreads();
        if (tid == 0) {
            int k = s_k, run = 0, g;
            for (g = 7; g > 0; g--) {
                if (run + wsum[g] >= k) break;
                run += wsum[g];
            }
            int bin;
            for (bin = g * 32 + 31; bin > g * 32; bin--) {
                if (run + hist[bin] >= k) break;
                run += hist[bin];
            }
            s_k = k - run;
            s_prefix = prefix | ((unsigned)bin << shift);
        }
        __syncthreads();
    }

    const unsigned kthkey = s_prefix;
    for (int i = tid; i < MM; i += 1024) {
        unsigned u = keys[i];
        bool sel = (u >= kthkey);
        unsigned smask = __ballot_sync(0xffffffffu, sel);
        if (sel) {
            int base = 0;
            if (lane == (__ffs(smask) - 1))
                base = atomicAdd(&s_cnt, __popc(smask));
            base = __shfl_sync(smask, base, __ffs(smask) - 1);
            int p = base + __popc(smask & ((1u << lane) - 1u));
            if (p < SEL_CAP) { s_idx[p] = i; s_w[p] = k2f(u); }
        }
    }
    __syncthreads();

    int n = s_cnt; if (n > SEL_CAP) n = SEL_CAP;

    // sum of w^2 (one warp)
    if (tid < 32) {
        float sw2 = 0.f;
        for (int i = tid; i < n; i += 32) { float w = s_w[i]; sw2 += w * w; }
        #pragma unroll
        for (int o = 16; o; o >>= 1) sw2 += __shfl_xor_sync(0xffffffffu, sw2, o);
        if (tid == 0) s_sw2 = sw2;
    }

    // read: 8 groups of 128 threads accumulate over selected rows (L2-hot)
    const int vcol = tid & (VV - 1);
    const int grp  = tid >> 7;
    float acc = 0.f;
    for (int i = grp; i < n; i += 8) {
        int   m = s_idx[i];
        float w = s_w[i];
        acc += w * mem[((size_t)b * MM + m) * VV + vcol];
    }
    s_part[grp][vcol] = acc;
    __syncthreads();

    if (tid < VV) {
        float a = 0.f;
        #pragma unroll
        for (int g = 0; g < 8; g++) a += s_part[g][tid];
        out[b * VV + tid] = a + s_sw2 * vin[b * VV + tid];
    }
}

// ============================================================================
extern "C" void kernel_launch(void* const* d_in, const int* in_sizes, int n_in,
                              void* d_out, int out_size) {
    const float* mem  = (const float*)d_in[0];   // (B, M, V) f32
    const float* vin  = (const float*)d_in[1];   // (B, V)    f32
    const int*   topk = (const int*)d_in[2];     // scalar    i32
    float*       out  = (float*)d_out;           // (B,1,1,V) f32

    sim_kernel<<<dim3(MM / 128, BB), 256>>>(mem, vin);
    select_read_kernel<<<BB, 1024>>>(topk, mem, vin, out);
}

// round 5
// speedup vs baseline: 1.1400x; 1.1400x over previous
#include <cuda_runtime.h>
#include <cstdint>
#include <math.h>

#define BB 64
#define MM 8192
#define VV 128
#define FEPS 1e-8f
#define SEL_CAP 1024

// Scratch (device globals: no allocation allowed in kernel_launch)
__device__ float g_sim[BB * MM];   // 2 MB similarity per slot

// ---- order-preserving float<->uint key mapping (larger float => larger key) ----
__device__ __forceinline__ unsigned f2k(float f) {
    unsigned b = __float_as_uint(f);
    return (b & 0x80000000u) ? ~b : (b | 0x80000000u);
}
__device__ __forceinline__ float k2f(unsigned u) {
    unsigned b = (u & 0x80000000u) ? (u ^ 0x80000000u) : ~u;
    return __uint_as_float(b);
}

// ============================================================================
// Pass 1: sim[b,m] = dot(mem[b,m]+eps, v[b]+eps) / max(||mem+eps||*||v+eps||, eps)
// 8 lanes per row, 4 rows per warp (coalesced 128B per row-segment), TWO tiles'
// loads batched up-front -> 8 independent LDG.128 in flight per thread.
// 256 threads -> 64 rows/block. Grid: (MM/64, BB).
// ============================================================================
__global__ void __launch_bounds__(256) sim_kernel(const float* __restrict__ mem,
                                                  const float* __restrict__ vin) {
    __shared__ __align__(16) float sv[VV];
    __shared__ float s_nb;
    const int b   = blockIdx.y;
    const int tid = threadIdx.x;

    if (tid < VV) sv[tid] = vin[b * VV + tid] + FEPS;
    __syncthreads();
    if (tid < 32) {
        float s = 0.f;
        #pragma unroll
        for (int i = tid; i < VV; i += 32) { float x = sv[i]; s += x * x; }
        #pragma unroll
        for (int o = 16; o; o >>= 1) s += __shfl_xor_sync(0xffffffffu, s, o);
        if (tid == 0) s_nb = sqrtf(s);
    }
    __syncthreads();

    const float nb   = s_nb;
    const int   warp = tid >> 5;
    const int   lane = tid & 31;
    const int   rw   = lane >> 3;   // row within warp's 4-row group
    const int   s    = lane & 7;    // float4 segment within row (0..7)

    const float4* svq = reinterpret_cast<const float4*>(sv);
    const float4 q0 = svq[s], q1 = svq[s + 8], q2 = svq[s + 16], q3 = svq[s + 24];

    const int m0 = blockIdx.x * 64 + warp * 4 + rw;
    const int m1 = m0 + 32;
    const float4* rowA = reinterpret_cast<const float4*>(mem + ((size_t)b * MM + m0) * VV);
    const float4* rowB = reinterpret_cast<const float4*>(mem + ((size_t)b * MM + m1) * VV);

    // 8 independent 16B loads in flight before any math
    float4 a0 = rowA[s];      float4 a1 = rowA[s + 8];
    float4 a2 = rowA[s + 16]; float4 a3 = rowA[s + 24];
    float4 b0 = rowB[s];      float4 b1 = rowB[s + 8];
    float4 b2 = rowB[s + 16]; float4 b3 = rowB[s + 24];

    float numA = 0.f, ssA = 0.f, numB = 0.f, ssB = 0.f;
    #define ACC(X, Q, NUM, SS)                                        \
        { float e0 = X.x + FEPS, e1 = X.y + FEPS,                     \
                e2 = X.z + FEPS, e3 = X.w + FEPS;                     \
          NUM += e0 * Q.x + e1 * Q.y + e2 * Q.z + e3 * Q.w;           \
          SS  += e0 * e0 + e1 * e1 + e2 * e2 + e3 * e3; }
    ACC(a0, q0, numA, ssA) ACC(a1, q1, numA, ssA)
    ACC(a2, q2, numA, ssA) ACC(a3, q3, numA, ssA)
    ACC(b0, q0, numB, ssB) ACC(b1, q1, numB, ssB)
    ACC(b2, q2, numB, ssB) ACC(b3, q3, numB, ssB)
    #undef ACC

    // reduce across the 8 lanes of each row (xor 1,2,4)
    #pragma unroll
    for (int o = 4; o; o >>= 1) {
        numA += __shfl_xor_sync(0xffffffffu, numA, o);
        ssA  += __shfl_xor_sync(0xffffffffu, ssA,  o);
        numB += __shfl_xor_sync(0xffffffffu, numB, o);
        ssB  += __shfl_xor_sync(0xffffffffu, ssB,  o);
    }
    if (s == 0) {
        g_sim[b * MM + m0] = numA / fmaxf(sqrtf(ssA) * nb, FEPS);
        g_sim[b * MM + m1] = numB / fmaxf(sqrtf(ssB) * nb, FEPS);
    }
}

// ============================================================================
// Pass 2 (fused select + read): per-batch exact kth-largest via 4-round 8-bit
// MSB radix select (plain shared atomics; HW aggregates same-address ATOMS),
// PARALLEL suffix-scan bin pick (no serial thread-0 chain), compaction, then
//   out[b,:] = sum_sel w*mem[b,m,:] + (sum_sel w^2)*v[b,:]
// One block of 1024 threads per batch.
// ============================================================================
__global__ void __launch_bounds__(1024) select_read_kernel(
        const int* __restrict__ topk_ptr,
        const float* __restrict__ mem,
        const float* __restrict__ vin,
        float* __restrict__ out) {
    __shared__ unsigned keys[MM];        // 32 KB
    __shared__ int      hist[256];
    __shared__ int      wsum[8];
    __shared__ unsigned s_prefix;
    __shared__ int      s_k, s_cnt;
    __shared__ int      s_idx[SEL_CAP];
    __shared__ float    s_w[SEL_CAP];
    __shared__ float    s_part[8][VV];   // 4 KB partial read accumulators
    __shared__ float    s_sw2;

    const int b    = blockIdx.x;
    const int tid  = threadIdx.x;
    const int lane = tid & 31;

    for (int i = tid; i < MM; i += 1024)
        keys[i] = f2k(g_sim[b * MM + i]);
    if (tid == 0) { s_prefix = 0u; s_k = *topk_ptr; s_cnt = 0; }
    __syncthreads();

    #pragma unroll
    for (int shift = 24; shift >= 0; shift -= 8) {
        if (tid < 256) hist[tid] = 0;
        __syncthreads();
        const unsigned pmask  = (shift == 24) ? 0u : (0xFFFFFFFFu << (shift + 8));
        const unsigned prefix = s_prefix;
        for (int i = tid; i < MM; i += 1024) {
            unsigned u = keys[i];
            if ((u & pmask) == prefix)
                atomicAdd(&hist[(u >> shift) & 255], 1);
        }
        __syncthreads();
        // Parallel suffix-sum over bins (descending): thread t handles bin r=255-t.
        // suf = hist[r] + hist[r+1] + ... + hist[255]
        {
            const int r = 255 - tid;             // valid for tid < 256
            int v = (tid < 256) ? hist[r] : 0;
            #pragma unroll
            for (int o = 1; o < 32; o <<= 1) {
                int t = __shfl_up_sync(0xffffffffu, v, o);
                if (lane >= o) v += t;
            }
            if (tid < 256 && lane == 31) wsum[tid >> 5] = v;
            __syncthreads();
            if (tid < 256) {
                int add = 0;
                #pragma unroll
                for (int w = 0; w < 8; w++) add += (w < (tid >> 5)) ? wsum[w] : 0;
                int suf = v + add;               // inclusive suffix count at bin r
                int k   = s_k;
                int above = suf - hist[r];       // count in bins strictly above r
                if (suf >= k && above < k) {     // exactly one thread fires
                    s_k = k - above;
                    s_prefix = prefix | ((unsigned)r << shift);
                }
            }
        }
        __syncthreads();
    }

    const unsigned kthkey = s_prefix;
    for (int i = tid; i < MM; i += 1024) {
        unsigned u = keys[i];
        if (u >= kthkey) {
            int p = atomicAdd(&s_cnt, 1);
            if (p < SEL_CAP) { s_idx[p] = i; s_w[p] = k2f(u); }
        }
    }
    __syncthreads();

    int n = s_cnt; if (n > SEL_CAP) n = SEL_CAP;

    // sum of w^2 (one warp)
    if (tid < 32) {
        float sw2 = 0.f;
        for (int i = tid; i < n; i += 32) { float w = s_w[i]; sw2 += w * w; }
        #pragma unroll
        for (int o = 16; o; o >>= 1) sw2 += __shfl_xor_sync(0xffffffffu, sw2, o);
        if (tid == 0) s_sw2 = sw2;
    }

    // read: 8 groups of 128 threads accumulate over selected rows
    const int vcol = tid & (VV - 1);
    const int grp  = tid >> 7;
    float acc = 0.f;
    for (int i = grp; i < n; i += 8) {
        int   m = s_idx[i];
        float w = s_w[i];
        acc += w * mem[((size_t)b * MM + m) * VV + vcol];
    }
    s_part[grp][vcol] = acc;
    __syncthreads();

    if (tid < VV) {
        float a = 0.f;
        #pragma unroll
        for (int g = 0; g < 8; g++) a += s_part[g][tid];
        out[b * VV + tid] = a + s_sw2 * vin[b * VV + tid];
    }
}

// ============================================================================
extern "C" void kernel_launch(void* const* d_in, const int* in_sizes, int n_in,
                              void* d_out, int out_size) {
    const float* mem  = (const float*)d_in[0];   // (B, M, V) f32
    const float* vin  = (const float*)d_in[1];   // (B, V)    f32
    const int*   topk = (const int*)d_in[2];     // scalar    i32
    float*       out  = (float*)d_out;           // (B,1,1,V) f32

    sim_kernel<<<dim3(MM / 64, BB), 256>>>(mem, vin);
    select_read_kernel<<<BB, 1024>>>(topk, mem, vin, out);
}

// round 6
// speedup vs baseline: 1.2803x; 1.1231x over previous
#include <cuda_runtime.h>
#include <cstdint>
#include <math.h>

#define BB 64
#define MM 8192
#define VV 128
#define FEPS 1e-8f
#define SEL_CAP 1024

// Scratch (device globals: no allocation allowed in kernel_launch)
__device__ float g_sim[BB * MM];   // 2 MB similarity per slot

// ---- order-preserving float<->uint key mapping (larger float => larger key) ----
__device__ __forceinline__ unsigned f2k(float f) {
    unsigned b = __float_as_uint(f);
    return (b & 0x80000000u) ? ~b : (b | 0x80000000u);
}
__device__ __forceinline__ float k2f(unsigned u) {
    unsigned b = (u & 0x80000000u) ? (u ^ 0x80000000u) : ~u;
    return __uint_as_float(b);
}

// ============================================================================
// Pass 1: sim[b,m] = dot(mem[b,m]+eps, v[b]+eps) / max(||mem+eps||*||v+eps||, eps)
// 8 lanes per row, 4 rows per warp (coalesced 128B per row-segment), TWO tiles'
// loads batched up-front -> 8 independent LDG.128 (streaming, evict-first) in
// flight per thread. 256 threads -> 64 rows/block. Grid: (MM/64, BB).
// ============================================================================
__global__ void __launch_bounds__(256) sim_kernel(const float* __restrict__ mem,
                                                  const float* __restrict__ vin) {
    __shared__ __align__(16) float sv[VV];
    __shared__ float s_nb;
    const int b   = blockIdx.y;
    const int tid = threadIdx.x;

    if (tid < VV) sv[tid] = vin[b * VV + tid] + FEPS;
    __syncthreads();
    if (tid < 32) {
        float s = 0.f;
        #pragma unroll
        for (int i = tid; i < VV; i += 32) { float x = sv[i]; s += x * x; }
        #pragma unroll
        for (int o = 16; o; o >>= 1) s += __shfl_xor_sync(0xffffffffu, s, o);
        if (tid == 0) s_nb = sqrtf(s);
    }
    __syncthreads();

    const float nb   = s_nb;
    const int   warp = tid >> 5;
    const int   lane = tid & 31;
    const int   rw   = lane >> 3;   // row within warp's 4-row group
    const int   s    = lane & 7;    // float4 segment within row (0..7)

    const float4* svq = reinterpret_cast<const float4*>(sv);
    const float4 q0 = svq[s], q1 = svq[s + 8], q2 = svq[s + 16], q3 = svq[s + 24];

    const int m0 = blockIdx.x * 64 + warp * 4 + rw;
    const int m1 = m0 + 32;
    const float4* rowA = reinterpret_cast<const float4*>(mem + ((size_t)b * MM + m0) * VV);
    const float4* rowB = reinterpret_cast<const float4*>(mem + ((size_t)b * MM + m1) * VV);

    // 8 independent streaming 16B loads in flight before any math
    float4 a0 = __ldcs(rowA + s);      float4 a1 = __ldcs(rowA + s + 8);
    float4 a2 = __ldcs(rowA + s + 16); float4 a3 = __ldcs(rowA + s + 24);
    float4 b0 = __ldcs(rowB + s);      float4 b1 = __ldcs(rowB + s + 8);
    float4 b2 = __ldcs(rowB + s + 16); float4 b3 = __ldcs(rowB + s + 24);

    float numA = 0.f, ssA = 0.f, numB = 0.f, ssB = 0.f;
    #define ACC(X, Q, NUM, SS)                                        \
        { float e0 = X.x + FEPS, e1 = X.y + FEPS,                     \
                e2 = X.z + FEPS, e3 = X.w + FEPS;                     \
          NUM += e0 * Q.x + e1 * Q.y + e2 * Q.z + e3 * Q.w;           \
          SS  += e0 * e0 + e1 * e1 + e2 * e2 + e3 * e3; }
    ACC(a0, q0, numA, ssA) ACC(a1, q1, numA, ssA)
    ACC(a2, q2, numA, ssA) ACC(a3, q3, numA, ssA)
    ACC(b0, q0, numB, ssB) ACC(b1, q1, numB, ssB)
    ACC(b2, q2, numB, ssB) ACC(b3, q3, numB, ssB)
    #undef ACC

    // reduce across the 8 lanes of each row (xor 1,2,4)
    #pragma unroll
    for (int o = 4; o; o >>= 1) {
        numA += __shfl_xor_sync(0xffffffffu, numA, o);
        ssA  += __shfl_xor_sync(0xffffffffu, ssA,  o);
        numB += __shfl_xor_sync(0xffffffffu, numB, o);
        ssB  += __shfl_xor_sync(0xffffffffu, ssB,  o);
    }
    if (s == 0) {
        g_sim[b * MM + m0] = numA / fmaxf(sqrtf(ssA) * nb, FEPS);
        g_sim[b * MM + m1] = numB / fmaxf(sqrtf(ssB) * nb, FEPS);
    }
}

// ============================================================================
// Pass 2 (fused select + read): keys live in REGISTERS (8 per thread, 1024
// threads = 8192 keys). 4-round 8-bit MSB radix select: each round is <=8
// predicated shared atomics per thread + a parallel suffix-scan bin pick.
// No smem key array, no LDS scans. Then compaction (from registers) and
//   out[b,:] = sum_sel w*mem[b,m,:] + (sum_sel w^2)*v[b,:]
// One block of 1024 threads per batch.
// ============================================================================
__global__ void __launch_bounds__(1024) select_read_kernel(
        const int* __restrict__ topk_ptr,
        const float* __restrict__ mem,
        const float* __restrict__ vin,
        float* __restrict__ out) {
    __shared__ int      hist[256];
    __shared__ int      wsum[8];
    __shared__ unsigned s_prefix;
    __shared__ int      s_k, s_cnt;
    __shared__ int      s_idx[SEL_CAP];
    __shared__ float    s_w[SEL_CAP];
    __shared__ float    s_part[8][VV];   // 4 KB partial read accumulators
    __shared__ float    s_sw2;

    const int b    = blockIdx.x;
    const int tid  = threadIdx.x;
    const int lane = tid & 31;

    // Load this thread's 8 keys into registers
    unsigned uk[8];
    #pragma unroll
    for (int j = 0; j < 8; j++)
        uk[j] = f2k(g_sim[b * MM + j * 1024 + tid]);

    if (tid == 0) { s_prefix = 0u; s_k = *topk_ptr; s_cnt = 0; }
    __syncthreads();

    #pragma unroll
    for (int shift = 24; shift >= 0; shift -= 8) {
        if (tid < 256) hist[tid] = 0;
        __syncthreads();
        const unsigned pmask  = (shift == 24) ? 0u : (0xFFFFFFFFu << (shift + 8));
        const unsigned prefix = s_prefix;
        #pragma unroll
        for (int j = 0; j < 8; j++) {
            unsigned u = uk[j];
            if ((u & pmask) == prefix)
                atomicAdd(&hist[(u >> shift) & 255], 1);
        }
        __syncthreads();
        // Parallel suffix-sum over bins (descending): thread t handles bin r=255-t.
        {
            const int r = 255 - tid;             // valid for tid < 256
            int v = (tid < 256) ? hist[r] : 0;
            #pragma unroll
            for (int o = 1; o < 32; o <<= 1) {
                int t = __shfl_up_sync(0xffffffffu, v, o);
                if (lane >= o) v += t;
            }
            if (tid < 256 && lane == 31) wsum[tid >> 5] = v;
            __syncthreads();
            if (tid < 256) {
                int add = 0;
                #pragma unroll
                for (int w = 0; w < 8; w++) add += (w < (tid >> 5)) ? wsum[w] : 0;
                int suf = v + add;               // inclusive suffix count at bin r
                int k   = s_k;
                int above = suf - hist[r];       // count in bins strictly above r
                if (suf >= k && above < k) {     // exactly one thread fires
                    s_k = k - above;
                    s_prefix = prefix | ((unsigned)r << shift);
                }
            }
        }
        __syncthreads();
    }

    const unsigned kthkey = s_prefix;
    #pragma unroll
    for (int j = 0; j < 8; j++) {
        unsigned u = uk[j];
        if (u >= kthkey) {
            int p = atomicAdd(&s_cnt, 1);
            if (p < SEL_CAP) { s_idx[p] = j * 1024 + tid; s_w[p] = k2f(u); }
        }
    }
    __syncthreads();

    int n = s_cnt; if (n > SEL_CAP) n = SEL_CAP;

    // sum of w^2 (one warp)
    if (tid < 32) {
        float sw2 = 0.f;
        for (int i = tid; i < n; i += 32) { float w = s_w[i]; sw2 += w * w; }
        #pragma unroll
        for (int o = 16; o; o >>= 1) sw2 += __shfl_xor_sync(0xffffffffu, sw2, o);
        if (tid == 0) s_sw2 = sw2;
    }

    // read: 8 groups of 128 threads accumulate over selected rows
    const int vcol = tid & (VV - 1);
    const int grp  = tid >> 7;
    float acc = 0.f;
    for (int i = grp; i < n; i += 8) {
        int   m = s_idx[i];
        float w = s_w[i];
        acc += w * mem[((size_t)b * MM + m) * VV + vcol];
    }
    s_part[grp][vcol] = acc;
    __syncthreads();

    if (tid < VV) {
        float a = 0.f;
        #pragma unroll
        for (int g = 0; g < 8; g++) a += s_part[g][tid];
        out[b * VV + tid] = a + s_sw2 * vin[b * VV + tid];
    }
}

// ============================================================================
extern "C" void kernel_launch(void* const* d_in, const int* in_sizes, int n_in,
                              void* d_out, int out_size) {
    const float* mem  = (const float*)d_in[0];   // (B, M, V) f32
    const float* vin  = (const float*)d_in[1];   // (B, V)    f32
    const int*   topk = (const int*)d_in[2];     // scalar    i32
    float*       out  = (float*)d_out;           // (B,1,1,V) f32

    sim_kernel<<<dim3(MM / 64, BB), 256>>>(mem, vin);
    select_read_kernel<<<BB, 1024>>>(topk, mem, vin, out);
}